// round 1
// baseline (speedup 1.0000x reference)
#include <cuda_runtime.h>

#define N_ENT  100000
#define N_EDGE 1600000
#define N_REL  64
#define N_TOT  (N_EDGE + N_ENT)   // 1,700,000 (even; exact grids below)

// Scratch (allocation-free rule: __device__ globals)
static __device__ float g_tailproj[N_ENT * 64];    // W_t · emb[n]
static __device__ float g_headrec [N_ENT * 128];   // [W_h·emb | M_h·emb]
static __device__ float g_self    [N_ENT * 128];   // [W_r·self_rel + b | M_r·self_rel]
static __device__ float g_arel    [N_REL * 64];    // W_r·emb_rel[r] + attn_b
static __device__ float g_mrel    [N_REL * 64];    // M_r·emb_rel[r]
static __device__ int   g_hist    [N_ENT * 64];    // per-node relation histogram
static __device__ float g_sum     [N_ENT * 8];     // softmax denominators
static __device__ float g_acc     [N_ENT * 64];    // unnormalized output accumulator

// ---------------------------------------------------------------------------
// Per-relation tables: a_rel[r] = attn_W[:,64:96]·emb_rel[r] + attn_b
//                      m_rel[r] = aggr_W[:,32:64]·emb_rel[r]
__global__ void rel_tables_kernel(const float* __restrict__ emb_rel,
                                  const float* __restrict__ attn_W,
                                  const float* __restrict__ attn_b,
                                  const float* __restrict__ aggr_W) {
    int r = threadIdx.x;
    if (r >= N_REL) return;
    float ev[32];
#pragma unroll
    for (int k = 0; k < 32; k++) ev[k] = emb_rel[r * 32 + k];
    for (int o = 0; o < 64; o++) {
        float a = attn_b[o], m = 0.f;
#pragma unroll
        for (int k = 0; k < 32; k++) {
            a = fmaf(attn_W[o * 96 + 64 + k], ev[k], a);
            m = fmaf(aggr_W[o * 64 + 32 + k], ev[k], m);
        }
        g_arel[r * 64 + o] = a;
        g_mrel[r * 64 + o] = m;
    }
}

// ---------------------------------------------------------------------------
// Per-node projections: one warp per node, lane = output dim (and dim+32)
__global__ void node_proj_kernel(const float* __restrict__ emb_ent,
                                 const float* __restrict__ attn_W,
                                 const float* __restrict__ aggr_W) {
    __shared__ float s_t[32 * 64], s_h[32 * 64], s_m[32 * 64];  // [k][o]
    for (int i = threadIdx.x; i < 2048; i += blockDim.x) {
        int k = i >> 6, o = i & 63;
        s_t[i] = attn_W[o * 96 + k];
        s_h[i] = attn_W[o * 96 + 32 + k];
        s_m[i] = aggr_W[o * 64 + k];
    }
    __syncthreads();
    int lane = threadIdx.x & 31;
    int warp = threadIdx.x >> 5;
    int wpb  = blockDim.x >> 5;
    for (int n = blockIdx.x * wpb + warp; n < N_ENT; n += gridDim.x * wpb) {
        float e = emb_ent[n * 32 + lane];
        float a0 = 0, a1 = 0, b0 = 0, b1 = 0, m0 = 0, m1 = 0;
#pragma unroll
        for (int k = 0; k < 32; k++) {
            float ek = __shfl_sync(0xffffffffu, e, k);
            a0 = fmaf(s_t[k * 64 + lane],      ek, a0);
            a1 = fmaf(s_t[k * 64 + 32 + lane], ek, a1);
            b0 = fmaf(s_h[k * 64 + lane],      ek, b0);
            b1 = fmaf(s_h[k * 64 + 32 + lane], ek, b1);
            m0 = fmaf(s_m[k * 64 + lane],      ek, m0);
            m1 = fmaf(s_m[k * 64 + 32 + lane], ek, m1);
        }
        g_tailproj[n * 64 + lane]       = a0;
        g_tailproj[n * 64 + 32 + lane]  = a1;
        g_headrec[n * 128 + lane]       = b0;
        g_headrec[n * 128 + 32 + lane]  = b1;
        g_headrec[n * 128 + 64 + lane]  = m0;
        g_headrec[n * 128 + 96 + lane]  = m1;
    }
}

// ---------------------------------------------------------------------------
// Relation histogram per tail node (one int atomic per edge)
__global__ void hist_kernel(const int* __restrict__ tail,
                            const int* __restrict__ rel) {
    int e = blockIdx.x * blockDim.x + threadIdx.x;
    if (e < N_EDGE) atomicAdd(&g_hist[tail[e] * 64 + rel[e]], 1);
}

// ---------------------------------------------------------------------------
// Self-loop records from histogram: one warp per node
__global__ void self_kernel() {
    int lane = threadIdx.x & 31;
    int n = blockIdx.x * (blockDim.x >> 5) + (threadIdx.x >> 5);
    if (n >= N_ENT) return;
    int h0 = g_hist[n * 64 + lane];
    int h1 = g_hist[n * 64 + 32 + lane];
    float inv = 1.f / (float)__reduce_add_sync(0xffffffffu, (unsigned)(h0 + h1));
    float fa0 = 0, fa1 = 0, fm0 = 0, fm1 = 0;
#pragma unroll
    for (int r = 0; r < 64; r++) {
        int hr = (r < 32) ? __shfl_sync(0xffffffffu, h0, r)
                          : __shfl_sync(0xffffffffu, h1, r - 32);
        if (hr) {
            float fh = (float)hr;
            fa0 = fmaf(fh, g_arel[r * 64 + lane],      fa0);
            fa1 = fmaf(fh, g_arel[r * 64 + 32 + lane], fa1);
            fm0 = fmaf(fh, g_mrel[r * 64 + lane],      fm0);
            fm1 = fmaf(fh, g_mrel[r * 64 + 32 + lane], fm1);
        }
    }
    g_self[n * 128 + lane]      = fa0 * inv;
    g_self[n * 128 + 32 + lane] = fa1 * inv;
    g_self[n * 128 + 64 + lane] = fm0 * inv;
    g_self[n * 128 + 96 + lane] = fm1 * inv;
}

// ---------------------------------------------------------------------------
// Fused edge pass: 16 lanes per edge (2 edges/warp). Computes exp(logit),
// atomically accumulates softmax denominator and exp-weighted message.
__global__ void edge_kernel(const int* __restrict__ head,
                            const int* __restrict__ tail,
                            const int* __restrict__ rel,
                            const float* __restrict__ attn_vec) {
    int gw   = (blockIdx.x * blockDim.x + threadIdx.x) >> 5;
    int lane = threadIdx.x & 31;
    int t    = lane & 15;
    int e    = gw * 2 + (lane >> 4);
    if (e >= N_TOT) return;   // never taken (exact grid); keeps shfl mask valid

    int hn, tn;
    const float *ar, *mr;
    if (e < N_EDGE) {
        hn = head[e]; tn = tail[e];
        int r = rel[e];
        ar = &g_arel[r * 64];
        mr = &g_mrel[r * 64];
    } else {
        int n = e - N_EDGE;
        hn = n; tn = n;
        ar = &g_self[n * 128];
        mr = &g_self[n * 128 + 64];
    }

    float4 at  = *(const float4*)(&g_tailproj[tn * 64 + 4 * t]);
    float4 ah  = *(const float4*)(&g_headrec[hn * 128 + 4 * t]);
    float4 mh  = *(const float4*)(&g_headrec[hn * 128 + 64 + 4 * t]);
    float4 arv = *(const float4*)(ar + 4 * t);
    float4 mrv = *(const float4*)(mr + 4 * t);
    float4 v   = *(const float4*)(&attn_vec[4 * t]);

    float p0 = at.x + ah.x + arv.x; p0 = fmaxf(p0, 0.2f * p0);  // leaky_relu
    float p1 = at.y + ah.y + arv.y; p1 = fmaxf(p1, 0.2f * p1);
    float p2 = at.z + ah.z + arv.z; p2 = fmaxf(p2, 0.2f * p2);
    float p3 = at.w + ah.w + arv.w; p3 = fmaxf(p3, 0.2f * p3);

    float s = p0 * v.x + p1 * v.y + p2 * v.z + p3 * v.w;
    s += __shfl_xor_sync(0xffffffffu, s, 1);      // head = t>>1 spans lane pairs
    float ex = __expf(s);                          // logits ~O(1): max-pass safe to skip

    if (!(t & 1)) atomicAdd(&g_sum[tn * 8 + (t >> 1)], ex);

    float mx = ex * (mh.x + mrv.x);
    float my = ex * (mh.y + mrv.y);
    float mz = ex * (mh.z + mrv.z);
    float mw = ex * (mh.w + mrv.w);
    float* dst = &g_acc[tn * 64 + 4 * t];
    asm volatile("red.global.add.v4.f32 [%0], {%1,%2,%3,%4};"
                 :: "l"(dst), "f"(mx), "f"(my), "f"(mz), "f"(mw) : "memory");
}

// ---------------------------------------------------------------------------
// out = acc / (sum + 1e-16) + aggr_b (bias commutes through softmax weights)
__global__ void final_kernel(float* __restrict__ out,
                             const float* __restrict__ aggr_b) {
    int i = blockIdx.x * blockDim.x + threadIdx.x;
    if (i >= N_ENT * 64) return;
    int n = i >> 6, j = i & 63;
    out[i] = g_acc[i] / (g_sum[n * 8 + (j >> 3)] + 1e-16f) + aggr_b[j];
}

// ---------------------------------------------------------------------------
extern "C" void kernel_launch(void* const* d_in, const int* in_sizes, int n_in,
                              void* d_out, int out_size) {
    const float* emb_ent  = (const float*)d_in[0];
    const float* emb_rel  = (const float*)d_in[1];
    const float* attn_W   = (const float*)d_in[2];
    const float* attn_b   = (const float*)d_in[3];
    const float* attn_vec = (const float*)d_in[4];
    const float* aggr_W   = (const float*)d_in[5];
    const float* aggr_b   = (const float*)d_in[6];
    const int*   head     = (const int*)d_in[7];
    const int*   tail     = (const int*)d_in[8];
    const int*   rel      = (const int*)d_in[9];
    float*       out      = (float*)d_out;

    void *p_hist, *p_sum, *p_acc;
    cudaGetSymbolAddress(&p_hist, g_hist);
    cudaGetSymbolAddress(&p_sum,  g_sum);
    cudaGetSymbolAddress(&p_acc,  g_acc);
    cudaMemsetAsync(p_hist, 0, sizeof(int)   * N_ENT * 64);
    cudaMemsetAsync(p_sum,  0, sizeof(float) * N_ENT * 8);
    cudaMemsetAsync(p_acc,  0, sizeof(float) * N_ENT * 64);

    rel_tables_kernel<<<1, 64>>>(emb_rel, attn_W, attn_b, aggr_W);
    node_proj_kernel<<<2048, 256>>>(emb_ent, attn_W, aggr_W);
    hist_kernel<<<(N_EDGE + 255) / 256, 256>>>(tail, rel);
    self_kernel<<<N_ENT / 8, 256>>>();
    edge_kernel<<<N_TOT / 16, 256>>>(head, tail, rel, attn_vec);
    final_kernel<<<(N_ENT * 64 + 255) / 256, 256>>>(out, aggr_b);
}